// round 1
// baseline (speedup 1.0000x reference)
#include <cuda_runtime.h>

#define EPSF      1e-7f
#define MAXNORM   (1.0f - 1e-5f)

#define BM 64
#define BK 16
#define BN 256
#define NTHREADS 256

// ---- packed f32x2 helpers (sm_103a) ----
__device__ __forceinline__ unsigned long long pack_dup(float x) {
    unsigned long long p;
    asm("mov.b64 %0, {%1, %1};" : "=l"(p) : "f"(x));
    return p;
}
__device__ __forceinline__ void unpack2(unsigned long long p, float& lo, float& hi) {
    asm("mov.b64 {%0, %1}, %2;" : "=f"(lo), "=f"(hi) : "l"(p));
}
__device__ __forceinline__ void ffma2(unsigned long long& d, unsigned long long a, unsigned long long b) {
    asm("fma.rn.f32x2 %0, %1, %2, %0;" : "+l"(d) : "l"(a), "l"(b));
}

__global__ __launch_bounds__(NTHREADS, 2)
void hyp_linear_kernel(const float* __restrict__ x,
                       const float* __restrict__ W,
                       const float* __restrict__ b,
                       float* __restrict__ out, int N)
{
    __shared__ __align__(16) unsigned long long xs[BK][BM]; // (v,v) duplicated pairs
    __shared__ __align__(16) float ws[BK][BN];              // W^T tile: ws[k][n]
    __shared__ float bsh[BN];
    __shared__ float xn2_sh[BM];
    __shared__ float warp_red[8];
    __shared__ float bn2_sh;

    const int tid  = threadIdx.x;
    const int lane = tid & 31;   // tx: column octet
    const int ty   = tid >> 5;   // row octet
    const int row0 = blockIdx.x * BM;

    // ---- bias -> smem, compute ||b||^2 once per block ----
    float bval = b[tid];
    bsh[tid] = bval;
    {
        float v = bval * bval;
        #pragma unroll
        for (int off = 16; off; off >>= 1) v += __shfl_xor_sync(0xffffffffu, v, off);
        if (lane == 0) warp_red[ty] = v;
    }
    __syncthreads();
    if (tid == 0) {
        float s = 0.f;
        #pragma unroll
        for (int i = 0; i < 8; ++i) s += warp_red[i];
        bn2_sh = s;
    }

    // ---- loader mapping: thread -> (row lr, k-seg lk) of the x tile ----
    const int lr = tid >> 2;          // [0,64)
    const int lk = (tid & 3) * 4;     // {0,4,8,12}
    int grow_l = row0 + lr;
    if (grow_l >= N) grow_l = N - 1;
    const float* xrow = x + (size_t)grow_l * 256;
    const float* wrow = W + (size_t)tid * 256;

    unsigned long long acc[8][4];
    #pragma unroll
    for (int i = 0; i < 8; ++i)
        #pragma unroll
        for (int j = 0; j < 4; ++j) acc[i][j] = 0ull;

    float xn2p = 0.f;

    // ---- main loop over K ----
    for (int kt = 0; kt < 256; kt += BK) {
        float4 xa = *reinterpret_cast<const float4*>(xrow + kt + lk);
        float4 w0 = *reinterpret_cast<const float4*>(wrow + kt + 0);
        float4 w1 = *reinterpret_cast<const float4*>(wrow + kt + 4);
        float4 w2 = *reinterpret_cast<const float4*>(wrow + kt + 8);
        float4 w3 = *reinterpret_cast<const float4*>(wrow + kt + 12);

        xn2p += xa.x*xa.x + xa.y*xa.y + xa.z*xa.z + xa.w*xa.w;

        __syncthreads();   // previous tile fully consumed
        xs[lk + 0][lr] = pack_dup(xa.x);
        xs[lk + 1][lr] = pack_dup(xa.y);
        xs[lk + 2][lr] = pack_dup(xa.z);
        xs[lk + 3][lr] = pack_dup(xa.w);
        ws[ 0][tid] = w0.x;  ws[ 1][tid] = w0.y;  ws[ 2][tid] = w0.z;  ws[ 3][tid] = w0.w;
        ws[ 4][tid] = w1.x;  ws[ 5][tid] = w1.y;  ws[ 6][tid] = w1.z;  ws[ 7][tid] = w1.w;
        ws[ 8][tid] = w2.x;  ws[ 9][tid] = w2.y;  ws[10][tid] = w2.z;  ws[11][tid] = w2.w;
        ws[12][tid] = w3.x;  ws[13][tid] = w3.y;  ws[14][tid] = w3.z;  ws[15][tid] = w3.w;
        __syncthreads();   // tile ready

        #pragma unroll
        for (int kk = 0; kk < BK; ++kk) {
            const unsigned long long* ap = &xs[kk][ty * 8];
            ulonglong2 a01 = *reinterpret_cast<const ulonglong2*>(ap + 0);
            ulonglong2 a23 = *reinterpret_cast<const ulonglong2*>(ap + 2);
            ulonglong2 a45 = *reinterpret_cast<const ulonglong2*>(ap + 4);
            ulonglong2 a67 = *reinterpret_cast<const ulonglong2*>(ap + 6);
            const float* bp = &ws[kk][lane * 8];
            ulonglong2 b01 = *reinterpret_cast<const ulonglong2*>(bp + 0);
            ulonglong2 b23 = *reinterpret_cast<const ulonglong2*>(bp + 4);

            unsigned long long av[8] = {a01.x, a01.y, a23.x, a23.y, a45.x, a45.y, a67.x, a67.y};
            unsigned long long bv[4] = {b01.x, b01.y, b23.x, b23.y};
            #pragma unroll
            for (int i = 0; i < 8; ++i)
                #pragma unroll
                for (int j = 0; j < 4; ++j)
                    ffma2(acc[i][j], av[i], bv[j]);
        }
    }

    // ---- reduce per-row ||x||^2 (4 loader threads per row; same warp, lanes 4i..4i+3) ----
    {
        float v = xn2p;
        v += __shfl_xor_sync(0xffffffffu, v, 1);
        v += __shfl_xor_sync(0xffffffffu, v, 2);
        if ((tid & 3) == 0) xn2_sh[lr] = v;
    }
    __syncthreads();

    // ---- fused epilogue ----
    const float bn2 = bn2_sh;
    const float bn  = sqrtf(bn2);
    float bcols[8];
    #pragma unroll
    for (int j = 0; j < 8; ++j) bcols[j] = bsh[lane * 8 + j];

    #pragma unroll
    for (int i = 0; i < 8; ++i) {
        float m[8];
        unpack2(acc[i][0], m[0], m[1]);
        unpack2(acc[i][1], m[2], m[3]);
        unpack2(acc[i][2], m[4], m[5]);
        unpack2(acc[i][3], m[6], m[7]);

        float q2 = 0.f, d = 0.f;
        #pragma unroll
        for (int j = 0; j < 8; ++j) { q2 += m[j] * m[j]; d += m[j] * bcols[j]; }
        #pragma unroll
        for (int off = 16; off; off >>= 1) {
            q2 += __shfl_xor_sync(0xffffffffu, q2, off);
            d  += __shfl_xor_sync(0xffffffffu, d,  off);
        }

        // per-row scalars (redundant across 32 lanes; cheap)
        float xn2 = xn2_sh[ty * 8 + i];
        float xn  = fmaxf(sqrtf(xn2), EPSF);
        float u   = fminf(xn, 1.0f - 1e-7f);
        float at  = 0.5f * (log1pf(u) - log1pf(-u));          // artanh(clip(xn))
        float mxn = fmaxf(sqrtf(q2), EPSF);
        float t   = tanhf(mxn / xn * at);
        t = fminf(t, MAXNORM);                                  // proj(res): ||res|| = t
        float alpha = t / mxn;                                  // res = alpha * mx
        float s  = 1.0f - t * t;                                // pt = s * b
        float vn  = fmaxf(s * bn, EPSF);
        float lam = 2.0f / fmaxf(s, EPSF);
        float beta = tanhf(0.5f * lam * vn) * s / vn;           // second = beta * b
        float xy = alpha * beta * d;
        float y2 = beta * beta * bn2;
        float A   = 1.0f + 2.0f * xy + y2;
        float den = fmaxf(1.0f + 2.0f * xy + (t * t) * y2, EPSF);
        float g1 = A * alpha / den;
        float g2 = s * beta  / den;
        // final proj
        float o2 = g1 * g1 * q2 + 2.0f * g1 * g2 * d + g2 * g2 * bn2;
        float on = fmaxf(sqrtf(o2), EPSF);
        if (on > MAXNORM) { float f = MAXNORM / on; g1 *= f; g2 *= f; }

        int grow = row0 + ty * 8 + i;
        if (grow < N) {
            float o[8];
            #pragma unroll
            for (int j = 0; j < 8; ++j) o[j] = g1 * m[j] + g2 * bcols[j];
            float* op = out + (size_t)grow * 256 + lane * 8;
            *reinterpret_cast<float4*>(op + 0) = make_float4(o[0], o[1], o[2], o[3]);
            *reinterpret_cast<float4*>(op + 4) = make_float4(o[4], o[5], o[6], o[7]);
        }
    }
}

extern "C" void kernel_launch(void* const* d_in, const int* in_sizes, int n_in,
                              void* d_out, int out_size) {
    const float* x = (const float*)d_in[0];
    const float* W = (const float*)d_in[1];
    const float* b = (const float*)d_in[2];
    float* out = (float*)d_out;
    int N = in_sizes[0] / 256;
    int grid = (N + BM - 1) / BM;
    hyp_linear_kernel<<<grid, NTHREADS>>>(x, W, b, out, N);
}

// round 3
// speedup vs baseline: 2.1812x; 2.1812x over previous
#include <cuda_runtime.h>
#include <cuda_bf16.h>
#include <cstdint>

#define EPSF    1e-7f
#define MAXNORM (1.0f - 1e-5f)

// ---------------- W pre-split (bf16 hi/lo, transposed to [k][n]) ----------------
__device__ unsigned short g_WhT[65536];   // [k][n]
__device__ unsigned short g_WlT[65536];
__device__ float g_bn2;

__global__ void wsplit_kernel(const float* __restrict__ W) {
    int i = blockIdx.x * blockDim.x + threadIdx.x;   // over W[n][k]
    int n = i >> 8, k = i & 255;
    float w = W[i];
    __nv_bfloat16 h = __float2bfloat16(w);
    float hf = __bfloat162float(h);
    __nv_bfloat16 l = __float2bfloat16(w - hf);
    g_WhT[k * 256 + n] = __bfloat16_as_ushort(h);
    g_WlT[k * 256 + n] = __bfloat16_as_ushort(l);
}

__global__ void bprep_kernel(const float* __restrict__ b) {
    __shared__ float red[8];
    int t = threadIdx.x;
    float v = b[t]; v *= v;
    #pragma unroll
    for (int off = 16; off; off >>= 1) v += __shfl_xor_sync(0xffffffffu, v, off);
    if ((t & 31) == 0) red[t >> 5] = v;
    __syncthreads();
    if (t == 0) {
        float s = 0.f;
        #pragma unroll
        for (int i = 0; i < 8; ++i) s += red[i];
        g_bn2 = s;
    }
}

// ---------------- PTX helpers (all compute_103-legal) ----------------
__device__ __forceinline__ uint32_t smem_u32(const void* p) {
    uint32_t a;
    asm("{ .reg .u64 t; cvta.to.shared.u64 t, %1; cvt.u32.u64 %0, t; }" : "=r"(a) : "l"(p));
    return a;
}
__device__ __forceinline__ void ldm_x4(uint32_t a, uint32_t& r0, uint32_t& r1, uint32_t& r2, uint32_t& r3) {
    asm volatile("ldmatrix.sync.aligned.m8n8.x4.shared.b16 {%0,%1,%2,%3}, [%4];"
                 : "=r"(r0), "=r"(r1), "=r"(r2), "=r"(r3) : "r"(a));
}
__device__ __forceinline__ void ldm_x4_t(uint32_t a, uint32_t& r0, uint32_t& r1, uint32_t& r2, uint32_t& r3) {
    asm volatile("ldmatrix.sync.aligned.m8n8.x4.trans.shared.b16 {%0,%1,%2,%3}, [%4];"
                 : "=r"(r0), "=r"(r1), "=r"(r2), "=r"(r3) : "r"(a));
}
__device__ __forceinline__ void mma16816(float* c, const uint32_t* a, const uint32_t* b) {
    asm volatile("mma.sync.aligned.m16n8k16.row.col.f32.bf16.bf16.f32 "
                 "{%0,%1,%2,%3}, {%4,%5,%6,%7}, {%8,%9}, {%0,%1,%2,%3};"
                 : "+f"(c[0]), "+f"(c[1]), "+f"(c[2]), "+f"(c[3])
                 : "r"(a[0]), "r"(a[1]), "r"(a[2]), "r"(a[3]), "r"(b[0]), "r"(b[1]));
}
__device__ __forceinline__ void cp16(uint32_t dst, const void* src) {
    asm volatile("cp.async.ca.shared.global [%0], [%1], 16;" :: "r"(dst), "l"(src) : "memory");
}
#define CP_COMMIT() asm volatile("cp.async.commit_group;" ::: "memory")
#define CP_WAIT1()  asm volatile("cp.async.wait_group 1;" ::: "memory")

// ---------------- smem layout ----------------
// A panels [m][k] bf16, row = 264 elems (528B, +8 pad -> ldmatrix conflict-free)
// B tiles  [k][n] bf16, row = 264 elems (528B), 32 k-rows per ktile
#define RA_B   528
#define A_SZ   67584          // 128*528
#define OFF_AHI 0
#define OFF_ALO 67584
#define OFF_B   135168        // [stage][panel]: stage stride 33792, panel 16896
#define BSTAGE  33792
#define BPANEL  16896
#define OFF_BIAS 202752
#define OFF_RQ   203776
#define OFF_RD   205824
#define OFF_XN2  207872
#define OFF_G1   208384
#define OFF_G2   208896
#define SMEM_TOTAL 209408

__global__ __launch_bounds__(256, 1)
void hyp_mma_kernel(const float* __restrict__ x, const float* __restrict__ b,
                    float* __restrict__ out, int N)
{
    extern __shared__ char smem[];
    const uint32_t sb = smem_u32(smem);
    const int tid = threadIdx.x, lane = tid & 31, wid = tid >> 5;
    const int wm = wid >> 2, wn = wid & 3;        // warp tile 64x64 in 2x4 grid
    const int row0 = blockIdx.x * 128;

    // ---- B tile issue (cp.async, 2-stage) ----
    auto issueB = [&](int kt, int s) {
        int r  = tid >> 3;                 // k-row 0..31
        int c0 = (tid & 7) * 4;            // 16B-chunk base (32 chunks per 512B row)
        const unsigned short* srch = g_WhT + (kt * 32 + r) * 256 + c0 * 8;
        const unsigned short* srcl = g_WlT + (kt * 32 + r) * 256 + c0 * 8;
        uint32_t dh = sb + OFF_B + s * BSTAGE + r * RA_B + c0 * 16;
        uint32_t dl = dh + BPANEL;
        #pragma unroll
        for (int j = 0; j < 4; ++j) {
            cp16(dh + j * 16, srch + j * 8);
            cp16(dl + j * 16, srcl + j * 8);
        }
        CP_COMMIT();
    };
    issueB(0, 0);
    issueB(1, 1);

    // ---- bias -> smem ----
    reinterpret_cast<float*>(smem + OFF_BIAS)[tid] = b[tid];

    // ---- x prologue: load, split bf16 hi/lo, STS, ||x||^2 ----
    {
        int r = tid >> 1;
        int halfc = (tid & 1) * 128;
        int gr = row0 + r; if (gr >= N) gr = N - 1;
        const float* xp = x + (size_t)gr * 256 + halfc;
        float xn2p = 0.f;
        #pragma unroll
        for (int i = 0; i < 16; ++i) {
            float4 v0 = *reinterpret_cast<const float4*>(xp + i * 8);
            float4 v1 = *reinterpret_cast<const float4*>(xp + i * 8 + 4);
            xn2p += v0.x*v0.x + v0.y*v0.y + v0.z*v0.z + v0.w*v0.w
                  + v1.x*v1.x + v1.y*v1.y + v1.z*v1.z + v1.w*v1.w;
            float v[8] = {v0.x, v0.y, v0.z, v0.w, v1.x, v1.y, v1.z, v1.w};
            uint32_t hp[4], lp[4];
            #pragma unroll
            for (int j = 0; j < 4; ++j) {
                __nv_bfloat16 h0 = __float2bfloat16(v[2*j]);
                __nv_bfloat16 h1 = __float2bfloat16(v[2*j+1]);
                __nv_bfloat16 l0 = __float2bfloat16(v[2*j]   - __bfloat162float(h0));
                __nv_bfloat16 l1 = __float2bfloat16(v[2*j+1] - __bfloat162float(h1));
                hp[j] = (uint32_t)__bfloat16_as_ushort(h1) << 16 | __bfloat16_as_ushort(h0);
                lp[j] = (uint32_t)__bfloat16_as_ushort(l1) << 16 | __bfloat16_as_ushort(l0);
            }
            uint32_t off = (uint32_t)r * RA_B + (uint32_t)(halfc + i * 8) * 2;
            *reinterpret_cast<uint4*>(smem + OFF_AHI + off) = make_uint4(hp[0], hp[1], hp[2], hp[3]);
            *reinterpret_cast<uint4*>(smem + OFF_ALO + off) = make_uint4(lp[0], lp[1], lp[2], lp[3]);
        }
        xn2p += __shfl_xor_sync(0xffffffffu, xn2p, 1);
        if (!(tid & 1)) reinterpret_cast<float*>(smem + OFF_XN2)[r] = xn2p;
    }

    // ---- accumulators ----
    float acc[4][8][4];
    #pragma unroll
    for (int mm = 0; mm < 4; ++mm)
        #pragma unroll
        for (int nn = 0; nn < 8; ++nn)
            #pragma unroll
            for (int q = 0; q < 4; ++q) acc[mm][nn][q] = 0.f;

    // lane-derived ldmatrix offsets
    const int arow  = (lane & 7) + ((lane & 8) ? 8 : 0);
    const uint32_t akoff = (lane & 16) ? 16 : 0;               // bytes
    const int bkrow = (lane & 7) + ((lane & 8) ? 8 : 0);
    const uint32_t bnoff = ((lane & 16) ? 8 : 0) * 2;          // bytes

    const uint32_t aHiBase = sb + OFF_AHI + (uint32_t)(wm * 64 + arow) * RA_B + akoff;
    const uint32_t aLoBase = aHiBase + (OFF_ALO - OFF_AHI);
    const uint32_t bColOff = (uint32_t)(wn * 64) * 2 + bnoff;

    // ---- main loop: 8 ktiles of 32 k ----
    for (int kt = 0; kt < 8; ++kt) {
        CP_WAIT1();
        __syncthreads();
        const uint32_t bHiBase = sb + OFF_B + (uint32_t)(kt & 1) * BSTAGE
                               + (uint32_t)bkrow * RA_B + bColOff;
        const uint32_t bLoBase = bHiBase + BPANEL;

        #pragma unroll
        for (int ks = 0; ks < 2; ++ks) {
            const uint32_t kbA = (uint32_t)(kt * 32 + ks * 16) * 2;
            const uint32_t kbB = (uint32_t)(ks * 16) * RA_B;

            uint32_t bh[8][2];
            #pragma unroll
            for (int nb = 0; nb < 4; ++nb)
                ldm_x4_t(bHiBase + kbB + (uint32_t)nb * 32,
                         bh[2*nb][0], bh[2*nb][1], bh[2*nb+1][0], bh[2*nb+1][1]);

            uint32_t ah[4][4];
            #pragma unroll
            for (int mm = 0; mm < 4; ++mm)
                ldm_x4(aHiBase + kbA + (uint32_t)mm * (16 * RA_B),
                       ah[mm][0], ah[mm][1], ah[mm][2], ah[mm][3]);

            #pragma unroll
            for (int mm = 0; mm < 4; ++mm)
                #pragma unroll
                for (int nn = 0; nn < 8; ++nn)
                    mma16816(acc[mm][nn], ah[mm], bh[nn]);

            uint32_t al[4][4];
            #pragma unroll
            for (int mm = 0; mm < 4; ++mm)
                ldm_x4(aLoBase + kbA + (uint32_t)mm * (16 * RA_B),
                       al[mm][0], al[mm][1], al[mm][2], al[mm][3]);
            #pragma unroll
            for (int mm = 0; mm < 4; ++mm)
                #pragma unroll
                for (int nn = 0; nn < 8; ++nn)
                    mma16816(acc[mm][nn], al[mm], bh[nn]);

            uint32_t bl[8][2];
            #pragma unroll
            for (int nb = 0; nb < 4; ++nb)
                ldm_x4_t(bLoBase + kbB + (uint32_t)nb * 32,
                         bl[2*nb][0], bl[2*nb][1], bl[2*nb+1][0], bl[2*nb+1][1]);
            #pragma unroll
            for (int mm = 0; mm < 4; ++mm)
                #pragma unroll
                for (int nn = 0; nn < 8; ++nn)
                    mma16816(acc[mm][nn], ah[mm], bl[nn]);
        }
        __syncthreads();
        if (kt < 6) issueB(kt + 2, kt & 1);
        else        CP_COMMIT();      // empty group keeps wait_group accounting exact
    }

    // ---- epilogue: per-row reductions ----
    const float* bias = reinterpret_cast<const float*>(smem + OFF_BIAS);
    float bb[8][2];
    #pragma unroll
    for (int nn = 0; nn < 8; ++nn) {
        int col = wn * 64 + nn * 8 + (lane & 3) * 2;
        bb[nn][0] = bias[col];
        bb[nn][1] = bias[col + 1];
    }
    float* rq  = reinterpret_cast<float*>(smem + OFF_RQ);
    float* rd  = reinterpret_cast<float*>(smem + OFF_RD);

    #pragma unroll
    for (int mm = 0; mm < 4; ++mm)
        #pragma unroll
        for (int hf = 0; hf < 2; ++hf) {
            float q2 = 0.f, d = 0.f;
            #pragma unroll
            for (int nn = 0; nn < 8; ++nn) {
                float v0 = acc[mm][nn][hf * 2 + 0];
                float v1 = acc[mm][nn][hf * 2 + 1];
                q2 += v0 * v0 + v1 * v1;
                d  += v0 * bb[nn][0] + v1 * bb[nn][1];
            }
            q2 += __shfl_xor_sync(0xffffffffu, q2, 1);
            q2 += __shfl_xor_sync(0xffffffffu, q2, 2);
            d  += __shfl_xor_sync(0xffffffffu, d, 1);
            d  += __shfl_xor_sync(0xffffffffu, d, 2);
            if ((lane & 3) == 0) {
                int row = wm * 64 + mm * 16 + (lane >> 2) + hf * 8;
                rq[row * 4 + wn] = q2;
                rd[row * 4 + wn] = d;
            }
        }
    __syncthreads();

    // ---- per-row scalar chain ----
    if (tid < 128) {
        int row = tid;
        float q2 = rq[row*4+0] + rq[row*4+1] + rq[row*4+2] + rq[row*4+3];
        float d  = rd[row*4+0] + rd[row*4+1] + rd[row*4+2] + rd[row*4+3];
        float xn2 = reinterpret_cast<float*>(smem + OFF_XN2)[row];
        float bn2 = g_bn2;
        float bn  = sqrtf(bn2);

        float xn  = fmaxf(sqrtf(xn2), EPSF);
        float u   = fminf(xn, 1.0f - 1e-7f);
        float at  = 0.5f * (log1pf(u) - log1pf(-u));
        float mxn = fmaxf(sqrtf(q2), EPSF);
        float t   = tanhf(mxn / xn * at);
        t = fminf(t, MAXNORM);
        float alpha = t / mxn;
        float s  = 1.0f - t * t;
        float vn = fmaxf(s * bn, EPSF);
        float lam = 2.0f / fmaxf(s, EPSF);
        float beta = tanhf(0.5f * lam * vn) * s / vn;
        float xy = alpha * beta * d;
        float y2 = beta * beta * bn2;
        float A   = 1.0f + 2.0f * xy + y2;
        float den = fmaxf(1.0f + 2.0f * xy + (t * t) * y2, EPSF);
        float g1 = A * alpha / den;
        float g2 = s * beta  / den;
        float o2 = g1 * g1 * q2 + 2.0f * g1 * g2 * d + g2 * g2 * bn2;
        float on = fmaxf(sqrtf(o2), EPSF);
        if (on > MAXNORM) { float f = MAXNORM / on; g1 *= f; g2 *= f; }
        reinterpret_cast<float*>(smem + OFF_G1)[row] = g1;
        reinterpret_cast<float*>(smem + OFF_G2)[row] = g2;
    }
    __syncthreads();

    // ---- scaled store ----
    const float* g1s = reinterpret_cast<const float*>(smem + OFF_G1);
    const float* g2s = reinterpret_cast<const float*>(smem + OFF_G2);
    #pragma unroll
    for (int mm = 0; mm < 4; ++mm)
        #pragma unroll
        for (int hf = 0; hf < 2; ++hf) {
            int row = wm * 64 + mm * 16 + (lane >> 2) + hf * 8;
            float g1 = g1s[row], g2 = g2s[row];
            int grow = row0 + row;
            if (grow < N) {
                float* orow = out + (size_t)grow * 256;
                #pragma unroll
                for (int nn = 0; nn < 8; ++nn) {
                    float2 v;
                    v.x = g1 * acc[mm][nn][hf * 2 + 0] + g2 * bb[nn][0];
                    v.y = g1 * acc[mm][nn][hf * 2 + 1] + g2 * bb[nn][1];
                    *reinterpret_cast<float2*>(orow + wn * 64 + nn * 8 + (lane & 3) * 2) = v;
                }
            }
        }
}

extern "C" void kernel_launch(void* const* d_in, const int* in_sizes, int n_in,
                              void* d_out, int out_size) {
    const float* x = (const float*)d_in[0];
    const float* W = (const float*)d_in[1];
    const float* b = (const float*)d_in[2];
    float* out = (float*)d_out;
    int N = in_sizes[0] / 256;

    cudaFuncSetAttribute(hyp_mma_kernel, cudaFuncAttributeMaxDynamicSharedMemorySize, SMEM_TOTAL);

    wsplit_kernel<<<256, 256>>>(W);
    bprep_kernel<<<1, 256>>>(b);
    int grid = (N + 127) / 128;
    hyp_mma_kernel<<<grid, 256, SMEM_TOTAL>>>(x, b, out, N);
}

// round 4
// speedup vs baseline: 2.3971x; 1.0990x over previous
#include <cuda_runtime.h>
#include <cuda_bf16.h>
#include <cstdint>

#define EPSF    1e-7f
#define MAXNORM (1.0f - 1e-5f)

// ---------------- W pre-split (bf16 hi/lo, transposed to [k][n]) ----------------
__device__ unsigned short g_WhT[65536];   // [k][n]
__device__ unsigned short g_WlT[65536];

// Coalesced transpose-split: 32x32 tiles via smem.
__global__ void wsplit_kernel(const float* __restrict__ W) {
    __shared__ unsigned short sh[32][36];
    __shared__ unsigned short sl[32][36];
    int bn0 = blockIdx.y * 32, bk0 = blockIdx.x * 32;
    int t = threadIdx.x;
    int r = t >> 3, c4 = (t & 7) * 4;
    float4 v = *reinterpret_cast<const float4*>(W + (bn0 + r) * 256 + bk0 + c4);
    float vv[4] = {v.x, v.y, v.z, v.w};
    #pragma unroll
    for (int j = 0; j < 4; ++j) {
        __nv_bfloat16 h = __float2bfloat16(vv[j]);
        __nv_bfloat16 l = __float2bfloat16(vv[j] - __bfloat162float(h));
        sh[c4 + j][r] = __bfloat16_as_ushort(h);   // [k][n] in tile
        sl[c4 + j][r] = __bfloat16_as_ushort(l);
    }
    __syncthreads();
    // write coalesced: row = k, 4 consecutive n per thread
    unsigned short ho[4], lo[4];
    #pragma unroll
    for (int j = 0; j < 4; ++j) { ho[j] = sh[r][c4 + j]; lo[j] = sl[r][c4 + j]; }
    *reinterpret_cast<uint2*>(g_WhT + (bk0 + r) * 256 + bn0 + c4) = *reinterpret_cast<uint2*>(ho);
    *reinterpret_cast<uint2*>(g_WlT + (bk0 + r) * 256 + bn0 + c4) = *reinterpret_cast<uint2*>(lo);
}

// ---------------- PTX helpers (compute_103-legal) ----------------
__device__ __forceinline__ uint32_t smem_u32(const void* p) {
    uint32_t a;
    asm("{ .reg .u64 t; cvta.to.shared.u64 t, %1; cvt.u32.u64 %0, t; }" : "=r"(a) : "l"(p));
    return a;
}
__device__ __forceinline__ void ldm_x4(uint32_t a, uint32_t& r0, uint32_t& r1, uint32_t& r2, uint32_t& r3) {
    asm volatile("ldmatrix.sync.aligned.m8n8.x4.shared.b16 {%0,%1,%2,%3}, [%4];"
                 : "=r"(r0), "=r"(r1), "=r"(r2), "=r"(r3) : "r"(a));
}
__device__ __forceinline__ void ldm_x4_t(uint32_t a, uint32_t& r0, uint32_t& r1, uint32_t& r2, uint32_t& r3) {
    asm volatile("ldmatrix.sync.aligned.m8n8.x4.trans.shared.b16 {%0,%1,%2,%3}, [%4];"
                 : "=r"(r0), "=r"(r1), "=r"(r2), "=r"(r3) : "r"(a));
}
__device__ __forceinline__ void mma16816(float* c, const uint32_t* a, const uint32_t* b) {
    asm volatile("mma.sync.aligned.m16n8k16.row.col.f32.bf16.bf16.f32 "
                 "{%0,%1,%2,%3}, {%4,%5,%6,%7}, {%8,%9}, {%0,%1,%2,%3};"
                 : "+f"(c[0]), "+f"(c[1]), "+f"(c[2]), "+f"(c[3])
                 : "r"(a[0]), "r"(a[1]), "r"(a[2]), "r"(a[3]), "r"(b[0]), "r"(b[1]));
}
__device__ __forceinline__ void cp16(uint32_t dst, const void* src) {
    asm volatile("cp.async.ca.shared.global [%0], [%1], 16;" :: "r"(dst), "l"(src) : "memory");
}
#define CP_COMMIT() asm volatile("cp.async.commit_group;" ::: "memory")
#define CP_WAIT1()  asm volatile("cp.async.wait_group 1;" ::: "memory")

// ---------------- smem layout ----------------
#define RA_B   528
#define OFF_AHI 0
#define OFF_ALO 67584
#define OFF_B   135168        // [stage][panel]: stage stride 33792, panel 16896
#define BSTAGE  33792
#define BPANEL  16896
#define OFF_BIAS 202752
#define OFF_RQ   203776
#define OFF_RD   205824
#define OFF_XN2  207872
#define OFF_G1   208384
#define OFF_G2   208896
#define OFF_BN2  209400
#define SMEM_TOTAL 209408

__global__ __launch_bounds__(512, 1)
void hyp_mma_kernel(const float* __restrict__ x, const float* __restrict__ b,
                    float* __restrict__ out, int N)
{
    extern __shared__ char smem[];
    const uint32_t sb = smem_u32(smem);
    const int tid = threadIdx.x, lane = tid & 31, wid = tid >> 5;
    const int wm = wid >> 2, wn = wid & 3;        // 4x4 warp grid, tile 32x64
    const int row0 = blockIdx.x * 128;

    // ---- B tile issue (cp.async, 2-stage), 512 threads ----
    auto issueB = [&](int kt, int s) {
        int r  = tid >> 4;                 // k-row 0..31
        int c0 = (tid & 15) * 16;          // elem base (16 elems per thread)
        const unsigned short* srch = g_WhT + (kt * 32 + r) * 256 + c0;
        const unsigned short* srcl = g_WlT + (kt * 32 + r) * 256 + c0;
        uint32_t dh = sb + OFF_B + s * BSTAGE + r * RA_B + c0 * 2;
        uint32_t dl = dh + BPANEL;
        cp16(dh,      srch);
        cp16(dh + 16, srch + 8);
        cp16(dl,      srcl);
        cp16(dl + 16, srcl + 8);
        CP_COMMIT();
    };
    issueB(0, 0);
    issueB(1, 1);

    // ---- bias -> smem ----
    if (tid < 256) reinterpret_cast<float*>(smem + OFF_BIAS)[tid] = b[tid];

    // ---- x prologue: 4 threads per row, 64 cols each ----
    {
        int r = tid >> 2;
        int qc = (tid & 3) * 64;
        int gr = row0 + r; if (gr >= N) gr = N - 1;
        const float* xp = x + (size_t)gr * 256 + qc;
        float xn2p = 0.f;
        #pragma unroll
        for (int i = 0; i < 8; ++i) {
            float4 v0 = *reinterpret_cast<const float4*>(xp + i * 8);
            float4 v1 = *reinterpret_cast<const float4*>(xp + i * 8 + 4);
            xn2p += v0.x*v0.x + v0.y*v0.y + v0.z*v0.z + v0.w*v0.w
                  + v1.x*v1.x + v1.y*v1.y + v1.z*v1.z + v1.w*v1.w;
            float v[8] = {v0.x, v0.y, v0.z, v0.w, v1.x, v1.y, v1.z, v1.w};
            uint32_t hp[4], lp[4];
            #pragma unroll
            for (int j = 0; j < 4; ++j) {
                __nv_bfloat16 h0 = __float2bfloat16(v[2*j]);
                __nv_bfloat16 h1 = __float2bfloat16(v[2*j+1]);
                __nv_bfloat16 l0 = __float2bfloat16(v[2*j]   - __bfloat162float(h0));
                __nv_bfloat16 l1 = __float2bfloat16(v[2*j+1] - __bfloat162float(h1));
                hp[j] = (uint32_t)__bfloat16_as_ushort(h1) << 16 | __bfloat16_as_ushort(h0);
                lp[j] = (uint32_t)__bfloat16_as_ushort(l1) << 16 | __bfloat16_as_ushort(l0);
            }
            uint32_t off = (uint32_t)r * RA_B + (uint32_t)(qc + i * 8) * 2;
            *reinterpret_cast<uint4*>(smem + OFF_AHI + off) = make_uint4(hp[0], hp[1], hp[2], hp[3]);
            *reinterpret_cast<uint4*>(smem + OFF_ALO + off) = make_uint4(lp[0], lp[1], lp[2], lp[3]);
        }
        xn2p += __shfl_xor_sync(0xffffffffu, xn2p, 1);
        xn2p += __shfl_xor_sync(0xffffffffu, xn2p, 2);
        if (!(tid & 3)) reinterpret_cast<float*>(smem + OFF_XN2)[r] = xn2p;
    }

    // ---- accumulators: warp tile 32x64 -> acc[2][8][4] ----
    float acc[2][8][4];
    #pragma unroll
    for (int mm = 0; mm < 2; ++mm)
        #pragma unroll
        for (int nn = 0; nn < 8; ++nn)
            #pragma unroll
            for (int q = 0; q < 4; ++q) acc[mm][nn][q] = 0.f;

    const int arow  = lane & 15;
    const uint32_t akoff = (lane & 16) ? 16 : 0;
    const int bkrow = lane & 15;
    const uint32_t bnoff = (lane & 16) ? 16 : 0;

    const uint32_t aHiBase = sb + OFF_AHI + (uint32_t)(wm * 32 + arow) * RA_B + akoff;
    const uint32_t aLoBase = aHiBase + (OFF_ALO - OFF_AHI);
    const uint32_t bColOff = (uint32_t)(wn * 64) * 2 + bnoff;

    // ---- main loop: 8 ktiles of 32 k ----
    for (int kt = 0; kt < 8; ++kt) {
        CP_WAIT1();
        __syncthreads();
        const uint32_t bHiBase = sb + OFF_B + (uint32_t)(kt & 1) * BSTAGE
                               + (uint32_t)bkrow * RA_B + bColOff;
        const uint32_t bLoBase = bHiBase + BPANEL;

        #pragma unroll
        for (int ks = 0; ks < 2; ++ks) {
            const uint32_t kbA = (uint32_t)(kt * 32 + ks * 16) * 2;
            const uint32_t kbB = (uint32_t)(ks * 16) * RA_B;

            uint32_t bh[8][2];
            #pragma unroll
            for (int nb = 0; nb < 4; ++nb)
                ldm_x4_t(bHiBase + kbB + (uint32_t)nb * 32,
                         bh[2*nb][0], bh[2*nb][1], bh[2*nb+1][0], bh[2*nb+1][1]);
            uint32_t ah[2][4];
            #pragma unroll
            for (int mm = 0; mm < 2; ++mm)
                ldm_x4(aHiBase + kbA + (uint32_t)mm * (16 * RA_B),
                       ah[mm][0], ah[mm][1], ah[mm][2], ah[mm][3]);

            #pragma unroll
            for (int mm = 0; mm < 2; ++mm)
                #pragma unroll
                for (int nn = 0; nn < 8; ++nn)
                    mma16816(acc[mm][nn], ah[mm], bh[nn]);

            {
                uint32_t al[2][4];
                #pragma unroll
                for (int mm = 0; mm < 2; ++mm)
                    ldm_x4(aLoBase + kbA + (uint32_t)mm * (16 * RA_B),
                           al[mm][0], al[mm][1], al[mm][2], al[mm][3]);
                #pragma unroll
                for (int mm = 0; mm < 2; ++mm)
                    #pragma unroll
                    for (int nn = 0; nn < 8; ++nn)
                        mma16816(acc[mm][nn], al[mm], bh[nn]);
            }
            {
                uint32_t bl[8][2];
                #pragma unroll
                for (int nb = 0; nb < 4; ++nb)
                    ldm_x4_t(bLoBase + kbB + (uint32_t)nb * 32,
                             bl[2*nb][0], bl[2*nb][1], bl[2*nb+1][0], bl[2*nb+1][1]);
                #pragma unroll
                for (int mm = 0; mm < 2; ++mm)
                    #pragma unroll
                    for (int nn = 0; nn < 8; ++nn)
                        mma16816(acc[mm][nn], ah[mm], bl[nn]);
            }
        }
        __syncthreads();
        if (kt < 6) issueB(kt + 2, kt & 1);
        else        CP_COMMIT();
    }

    // ---- epilogue: per-row reductions ----
    const float* bias = reinterpret_cast<const float*>(smem + OFF_BIAS);
    float bb[8][2];
    #pragma unroll
    for (int nn = 0; nn < 8; ++nn) {
        int col = wn * 64 + nn * 8 + (lane & 3) * 2;
        bb[nn][0] = bias[col];
        bb[nn][1] = bias[col + 1];
    }
    float* rq = reinterpret_cast<float*>(smem + OFF_RQ);
    float* rd = reinterpret_cast<float*>(smem + OFF_RD);

    #pragma unroll
    for (int mm = 0; mm < 2; ++mm)
        #pragma unroll
        for (int hf = 0; hf < 2; ++hf) {
            float q2 = 0.f, d = 0.f;
            #pragma unroll
            for (int nn = 0; nn < 8; ++nn) {
                float v0 = acc[mm][nn][hf * 2 + 0];
                float v1 = acc[mm][nn][hf * 2 + 1];
                q2 += v0 * v0 + v1 * v1;
                d  += v0 * bb[nn][0] + v1 * bb[nn][1];
            }
            q2 += __shfl_xor_sync(0xffffffffu, q2, 1);
            q2 += __shfl_xor_sync(0xffffffffu, q2, 2);
            d  += __shfl_xor_sync(0xffffffffu, d, 1);
            d  += __shfl_xor_sync(0xffffffffu, d, 2);
            if ((lane & 3) == 0) {
                int row = wm * 32 + mm * 16 + (lane >> 2) + hf * 8;
                rq[row * 4 + wn] = q2;
                rd[row * 4 + wn] = d;
            }
        }

    // ||b||^2 once per CTA (warp 0)
    if (wid == 0) {
        float v = bias[lane] * bias[lane]
                + bias[lane + 32] * bias[lane + 32]
                + bias[lane + 64] * bias[lane + 64]
                + bias[lane + 96] * bias[lane + 96]
                + bias[lane + 128] * bias[lane + 128]
                + bias[lane + 160] * bias[lane + 160]
                + bias[lane + 192] * bias[lane + 192]
                + bias[lane + 224] * bias[lane + 224];
        #pragma unroll
        for (int off = 16; off; off >>= 1) v += __shfl_xor_sync(0xffffffffu, v, off);
        if (lane == 0) *reinterpret_cast<float*>(smem + OFF_BN2) = v;
    }
    __syncthreads();

    // ---- per-row scalar chain ----
    if (tid < 128) {
        int row = tid;
        float q2 = rq[row*4+0] + rq[row*4+1] + rq[row*4+2] + rq[row*4+3];
        float d  = rd[row*4+0] + rd[row*4+1] + rd[row*4+2] + rd[row*4+3];
        float xn2 = reinterpret_cast<float*>(smem + OFF_XN2)[row];
        float bn2 = *reinterpret_cast<float*>(smem + OFF_BN2);
        float bn  = sqrtf(bn2);

        float xn  = fmaxf(sqrtf(xn2), EPSF);
        float u   = fminf(xn, 1.0f - 1e-7f);
        float at  = 0.5f * (log1pf(u) - log1pf(-u));
        float mxn = fmaxf(sqrtf(q2), EPSF);
        float t   = tanhf(mxn / xn * at);
        t = fminf(t, MAXNORM);
        float alpha = t / mxn;
        float s  = 1.0f - t * t;
        float vn = fmaxf(s * bn, EPSF);
        float lam = 2.0f / fmaxf(s, EPSF);
        float beta = tanhf(0.5f * lam * vn) * s / vn;
        float xy = alpha * beta * d;
        float y2 = beta * beta * bn2;
        float A   = 1.0f + 2.0f * xy + y2;
        float den = fmaxf(1.0f + 2.0f * xy + (t * t) * y2, EPSF);
        float g1 = A * alpha / den;
        float g2 = s * beta  / den;
        float o2 = g1 * g1 * q2 + 2.0f * g1 * g2 * d + g2 * g2 * bn2;
        float on = fmaxf(sqrtf(o2), EPSF);
        if (on > MAXNORM) { float f = MAXNORM / on; g1 *= f; g2 *= f; }
        reinterpret_cast<float*>(smem + OFF_G1)[row] = g1;
        reinterpret_cast<float*>(smem + OFF_G2)[row] = g2;
    }
    __syncthreads();

    // ---- scaled store ----
    const float* g1s = reinterpret_cast<const float*>(smem + OFF_G1);
    const float* g2s = reinterpret_cast<const float*>(smem + OFF_G2);
    #pragma unroll
    for (int mm = 0; mm < 2; ++mm)
        #pragma unroll
        for (int hf = 0; hf < 2; ++hf) {
            int row = wm * 32 + mm * 16 + (lane >> 2) + hf * 8;
            float g1 = g1s[row], g2 = g2s[row];
            int grow = row0 + row;
            if (grow < N) {
                float* orow = out + (size_t)grow * 256;
                #pragma unroll
                for (int nn = 0; nn < 8; ++nn) {
                    float2 v;
                    v.x = g1 * acc[mm][nn][hf * 2 + 0] + g2 * bb[nn][0];
                    v.y = g1 * acc[mm][nn][hf * 2 + 1] + g2 * bb[nn][1];
                    *reinterpret_cast<float2*>(orow + wn * 64 + nn * 8 + (lane & 3) * 2) = v;
                }
            }
        }
}

extern "C" void kernel_launch(void* const* d_in, const int* in_sizes, int n_in,
                              void* d_out, int out_size) {
    const float* x = (const float*)d_in[0];
    const float* W = (const float*)d_in[1];
    const float* b = (const float*)d_in[2];
    float* out = (float*)d_out;
    int N = in_sizes[0] / 256;

    cudaFuncSetAttribute(hyp_mma_kernel, cudaFuncAttributeMaxDynamicSharedMemorySize, SMEM_TOTAL);

    dim3 wgrid(8, 8);
    wsplit_kernel<<<wgrid, 256>>>(W);
    int grid = (N + 127) / 128;
    hyp_mma_kernel<<<grid, 512, SMEM_TOTAL>>>(x, b, out, N);
}

// round 5
// speedup vs baseline: 2.7594x; 1.1511x over previous
#include <cuda_runtime.h>
#include <cuda_bf16.h>
#include <cstdint>

#define EPSF    1e-7f
#define MAXNORM (1.0f - 1e-5f)

// ---------------- W pre-split (bf16 hi/lo, transposed to [k][n]) ----------------
__device__ unsigned short g_WhT[65536];   // [k][n]
__device__ unsigned short g_WlT[65536];

__global__ void wsplit_kernel(const float* __restrict__ W) {
    __shared__ unsigned short sh[32][36];
    __shared__ unsigned short sl[32][36];
    int bn0 = blockIdx.y * 32, bk0 = blockIdx.x * 32;
    int t = threadIdx.x;
    int r = t >> 3, c4 = (t & 7) * 4;
    float4 v = *reinterpret_cast<const float4*>(W + (bn0 + r) * 256 + bk0 + c4);
    float vv[4] = {v.x, v.y, v.z, v.w};
    #pragma unroll
    for (int j = 0; j < 4; ++j) {
        __nv_bfloat16 h = __float2bfloat16(vv[j]);
        __nv_bfloat16 l = __float2bfloat16(vv[j] - __bfloat162float(h));
        sh[c4 + j][r] = __bfloat16_as_ushort(h);
        sl[c4 + j][r] = __bfloat16_as_ushort(l);
    }
    __syncthreads();
    unsigned short ho[4], lo[4];
    #pragma unroll
    for (int j = 0; j < 4; ++j) { ho[j] = sh[r][c4 + j]; lo[j] = sl[r][c4 + j]; }
    *reinterpret_cast<uint2*>(g_WhT + (bk0 + r) * 256 + bn0 + c4) = *reinterpret_cast<uint2*>(ho);
    *reinterpret_cast<uint2*>(g_WlT + (bk0 + r) * 256 + bn0 + c4) = *reinterpret_cast<uint2*>(lo);
}

// ---------------- PTX helpers ----------------
__device__ __forceinline__ uint32_t smem_u32(const void* p) {
    uint32_t a;
    asm("{ .reg .u64 t; cvta.to.shared.u64 t, %1; cvt.u32.u64 %0, t; }" : "=r"(a) : "l"(p));
    return a;
}
__device__ __forceinline__ void ldm_x4(uint32_t a, uint32_t& r0, uint32_t& r1, uint32_t& r2, uint32_t& r3) {
    asm volatile("ldmatrix.sync.aligned.m8n8.x4.shared.b16 {%0,%1,%2,%3}, [%4];"
                 : "=r"(r0), "=r"(r1), "=r"(r2), "=r"(r3) : "r"(a));
}
__device__ __forceinline__ void ldm_x4_t(uint32_t a, uint32_t& r0, uint32_t& r1, uint32_t& r2, uint32_t& r3) {
    asm volatile("ldmatrix.sync.aligned.m8n8.x4.trans.shared.b16 {%0,%1,%2,%3}, [%4];"
                 : "=r"(r0), "=r"(r1), "=r"(r2), "=r"(r3) : "r"(a));
}
__device__ __forceinline__ void mma16816(float* c, const uint32_t* a, const uint32_t* b) {
    asm volatile("mma.sync.aligned.m16n8k16.row.col.f32.bf16.bf16.f32 "
                 "{%0,%1,%2,%3}, {%4,%5,%6,%7}, {%8,%9}, {%0,%1,%2,%3};"
                 : "+f"(c[0]), "+f"(c[1]), "+f"(c[2]), "+f"(c[3])
                 : "r"(a[0]), "r"(a[1]), "r"(a[2]), "r"(a[3]), "r"(b[0]), "r"(b[1]));
}
__device__ __forceinline__ void cp16(uint32_t dst, const void* src) {
    asm volatile("cp.async.ca.shared.global [%0], [%1], 16;" :: "r"(dst), "l"(src) : "memory");
}
#define CP_COMMIT() asm volatile("cp.async.commit_group;" ::: "memory")
#define CP_WAIT1()  asm volatile("cp.async.wait_group 1;" ::: "memory")

// ---------------- smem layout (per 64-row CTA) ----------------
#define RA_B    528
#define OFF_AHI 0          // 64*528 = 33792
#define OFF_ALO 33792
#define OFF_B   67584      // 2 stages x (hi 8448 + lo 8448)
#define BSTAGE  16896
#define BPANEL  8448
#define OFF_BIAS 101376
#define OFF_RQ   102400
#define OFF_RD   103424
#define OFF_XN2  104448
#define OFF_G1   104704
#define OFF_G2   104960
#define OFF_BN2  105216
#define SMEM_TOTAL 105472

__global__ __launch_bounds__(256, 2)
void hyp_mma_kernel(const float* __restrict__ x, const float* __restrict__ b,
                    float* __restrict__ out, int N)
{
    extern __shared__ char smem[];
    const uint32_t sb = smem_u32(smem);
    const int tid = threadIdx.x, lane = tid & 31, wid = tid >> 5;
    const int wm = wid >> 2, wn = wid & 3;        // 2x4 warp grid, tile 32x64
    const int row0 = blockIdx.x * 64;

    // ---- B ktile issue (k16, 2-stage), 256 threads ----
    auto issueB = [&](int kt, int s) {
        int r  = tid >> 4;                 // k-row 0..15
        int ci = tid & 15;                 // 32B chunk (2x cp16) per panel row
        const unsigned short* srch = g_WhT + (kt * 16 + r) * 256 + ci * 16;
        const unsigned short* srcl = g_WlT + (kt * 16 + r) * 256 + ci * 16;
        uint32_t dh = sb + OFF_B + s * BSTAGE + r * RA_B + ci * 32;
        uint32_t dl = dh + BPANEL;
        cp16(dh,      srch);
        cp16(dh + 16, srch + 8);
        cp16(dl,      srcl);
        cp16(dl + 16, srcl + 8);
        CP_COMMIT();
    };
    issueB(0, 0);
    issueB(1, 1);

    // ---- bias -> smem ----
    reinterpret_cast<float*>(smem + OFF_BIAS)[tid] = b[tid];

    // ---- x prologue: 4 threads per row, 64 cols each ----
    {
        int r = tid >> 2;
        int qc = (tid & 3) * 64;
        int gr = row0 + r; if (gr >= N) gr = N - 1;
        const float* xp = x + (size_t)gr * 256 + qc;
        float xn2p = 0.f;
        #pragma unroll
        for (int i = 0; i < 8; ++i) {
            float4 v0 = *reinterpret_cast<const float4*>(xp + i * 8);
            float4 v1 = *reinterpret_cast<const float4*>(xp + i * 8 + 4);
            xn2p += v0.x*v0.x + v0.y*v0.y + v0.z*v0.z + v0.w*v0.w
                  + v1.x*v1.x + v1.y*v1.y + v1.z*v1.z + v1.w*v1.w;
            float v[8] = {v0.x, v0.y, v0.z, v0.w, v1.x, v1.y, v1.z, v1.w};
            uint32_t hp[4], lp[4];
            #pragma unroll
            for (int j = 0; j < 4; ++j) {
                __nv_bfloat16 h0 = __float2bfloat16(v[2*j]);
                __nv_bfloat16 h1 = __float2bfloat16(v[2*j+1]);
                __nv_bfloat16 l0 = __float2bfloat16(v[2*j]   - __bfloat162float(h0));
                __nv_bfloat16 l1 = __float2bfloat16(v[2*j+1] - __bfloat162float(h1));
                hp[j] = (uint32_t)__bfloat16_as_ushort(h1) << 16 | __bfloat16_as_ushort(h0);
                lp[j] = (uint32_t)__bfloat16_as_ushort(l1) << 16 | __bfloat16_as_ushort(l0);
            }
            uint32_t off = (uint32_t)r * RA_B + (uint32_t)(qc + i * 8) * 2;
            *reinterpret_cast<uint4*>(smem + OFF_AHI + off) = make_uint4(hp[0], hp[1], hp[2], hp[3]);
            *reinterpret_cast<uint4*>(smem + OFF_ALO + off) = make_uint4(lp[0], lp[1], lp[2], lp[3]);
        }
        xn2p += __shfl_xor_sync(0xffffffffu, xn2p, 1);
        xn2p += __shfl_xor_sync(0xffffffffu, xn2p, 2);
        if (!(tid & 3)) reinterpret_cast<float*>(smem + OFF_XN2)[r] = xn2p;
    }

    // ---- accumulators: warp tile 32x64 ----
    float acc[2][8][4];
    #pragma unroll
    for (int mm = 0; mm < 2; ++mm)
        #pragma unroll
        for (int nn = 0; nn < 8; ++nn)
            #pragma unroll
            for (int q = 0; q < 4; ++q) acc[mm][nn][q] = 0.f;

    const int arow  = lane & 15;
    const uint32_t akoff = (lane & 16) ? 16 : 0;
    const int bkrow = lane & 15;
    const uint32_t bnoff = (lane & 16) ? 16 : 0;

    const uint32_t aHiBase = sb + OFF_AHI + (uint32_t)(wm * 32 + arow) * RA_B + akoff;
    const uint32_t aLoBase = aHiBase + (OFF_ALO - OFF_AHI);
    const uint32_t bColOff = (uint32_t)(wn * 64) * 2 + bnoff;

    // ---- main loop: 16 ktiles of k16 ----
    for (int kt = 0; kt < 16; ++kt) {
        CP_WAIT1();
        __syncthreads();
        const uint32_t bHiBase = sb + OFF_B + (uint32_t)(kt & 1) * BSTAGE
                               + (uint32_t)bkrow * RA_B + bColOff;
        const uint32_t bLoBase = bHiBase + BPANEL;
        const uint32_t kbA = (uint32_t)kt * 32;   // kt*16 elems * 2B

        uint32_t bh[8][2];
        #pragma unroll
        for (int nb = 0; nb < 4; ++nb)
            ldm_x4_t(bHiBase + (uint32_t)nb * 32,
                     bh[2*nb][0], bh[2*nb][1], bh[2*nb+1][0], bh[2*nb+1][1]);
        uint32_t ah[2][4];
        #pragma unroll
        for (int mm = 0; mm < 2; ++mm)
            ldm_x4(aHiBase + kbA + (uint32_t)mm * (16 * RA_B),
                   ah[mm][0], ah[mm][1], ah[mm][2], ah[mm][3]);

        #pragma unroll
        for (int mm = 0; mm < 2; ++mm)
            #pragma unroll
            for (int nn = 0; nn < 8; ++nn)
                mma16816(acc[mm][nn], ah[mm], bh[nn]);

        {
            uint32_t al[2][4];
            #pragma unroll
            for (int mm = 0; mm < 2; ++mm)
                ldm_x4(aLoBase + kbA + (uint32_t)mm * (16 * RA_B),
                       al[mm][0], al[mm][1], al[mm][2], al[mm][3]);
            #pragma unroll
            for (int mm = 0; mm < 2; ++mm)
                #pragma unroll
                for (int nn = 0; nn < 8; ++nn)
                    mma16816(acc[mm][nn], al[mm], bh[nn]);
        }
        {
            uint32_t bl[8][2];
            #pragma unroll
            for (int nb = 0; nb < 4; ++nb)
                ldm_x4_t(bLoBase + (uint32_t)nb * 32,
                         bl[2*nb][0], bl[2*nb][1], bl[2*nb+1][0], bl[2*nb+1][1]);
            #pragma unroll
            for (int mm = 0; mm < 2; ++mm)
                #pragma unroll
                for (int nn = 0; nn < 8; ++nn)
                    mma16816(acc[mm][nn], ah[mm], bl[nn]);
        }
        __syncthreads();
        if (kt < 14) issueB(kt + 2, kt & 1);
        else         CP_COMMIT();
    }

    // ---- epilogue: per-row reductions ----
    const float* bias = reinterpret_cast<const float*>(smem + OFF_BIAS);
    float bb[8][2];
    #pragma unroll
    for (int nn = 0; nn < 8; ++nn) {
        int col = wn * 64 + nn * 8 + (lane & 3) * 2;
        bb[nn][0] = bias[col];
        bb[nn][1] = bias[col + 1];
    }
    float* rq = reinterpret_cast<float*>(smem + OFF_RQ);
    float* rd = reinterpret_cast<float*>(smem + OFF_RD);

    #pragma unroll
    for (int mm = 0; mm < 2; ++mm)
        #pragma unroll
        for (int hf = 0; hf < 2; ++hf) {
            float q2 = 0.f, d = 0.f;
            #pragma unroll
            for (int nn = 0; nn < 8; ++nn) {
                float v0 = acc[mm][nn][hf * 2 + 0];
                float v1 = acc[mm][nn][hf * 2 + 1];
                q2 += v0 * v0 + v1 * v1;
                d  += v0 * bb[nn][0] + v1 * bb[nn][1];
            }
            q2 += __shfl_xor_sync(0xffffffffu, q2, 1);
            q2 += __shfl_xor_sync(0xffffffffu, q2, 2);
            d  += __shfl_xor_sync(0xffffffffu, d, 1);
            d  += __shfl_xor_sync(0xffffffffu, d, 2);
            if ((lane & 3) == 0) {
                int row = wm * 32 + mm * 16 + (lane >> 2) + hf * 8;
                rq[row * 4 + wn] = q2;
                rd[row * 4 + wn] = d;
            }
        }

    // ||b||^2 once per CTA (warp 0)
    if (wid == 0) {
        float v = 0.f;
        #pragma unroll
        for (int i = 0; i < 8; ++i) {
            float bv = bias[lane + i * 32];
            v += bv * bv;
        }
        #pragma unroll
        for (int off = 16; off; off >>= 1) v += __shfl_xor_sync(0xffffffffu, v, off);
        if (lane == 0) *reinterpret_cast<float*>(smem + OFF_BN2) = v;
    }
    __syncthreads();

    // ---- per-row scalar chain ----
    if (tid < 64) {
        int row = tid;
        float q2 = rq[row*4+0] + rq[row*4+1] + rq[row*4+2] + rq[row*4+3];
        float d  = rd[row*4+0] + rd[row*4+1] + rd[row*4+2] + rd[row*4+3];
        float xn2 = reinterpret_cast<float*>(smem + OFF_XN2)[row];
        float bn2 = *reinterpret_cast<float*>(smem + OFF_BN2);
        float bn  = sqrtf(bn2);

        float xn  = fmaxf(sqrtf(xn2), EPSF);
        float u   = fminf(xn, 1.0f - 1e-7f);
        float at  = 0.5f * (log1pf(u) - log1pf(-u));
        float mxn = fmaxf(sqrtf(q2), EPSF);
        float t   = tanhf(mxn / xn * at);
        t = fminf(t, MAXNORM);
        float alpha = t / mxn;
        float s  = 1.0f - t * t;
        float vn = fmaxf(s * bn, EPSF);
        float lam = 2.0f / fmaxf(s, EPSF);
        float beta = tanhf(0.5f * lam * vn) * s / vn;
        float xy = alpha * beta * d;
        float y2 = beta * beta * bn2;
        float A   = 1.0f + 2.0f * xy + y2;
        float den = fmaxf(1.0f + 2.0f * xy + (t * t) * y2, EPSF);
        float g1 = A * alpha / den;
        float g2 = s * beta  / den;
        float o2 = g1 * g1 * q2 + 2.0f * g1 * g2 * d + g2 * g2 * bn2;
        float on = fmaxf(sqrtf(o2), EPSF);
        if (on > MAXNORM) { float f = MAXNORM / on; g1 *= f; g2 *= f; }
        reinterpret_cast<float*>(smem + OFF_G1)[row] = g1;
        reinterpret_cast<float*>(smem + OFF_G2)[row] = g2;
    }
    __syncthreads();

    // ---- scaled store ----
    const float* g1s = reinterpret_cast<const float*>(smem + OFF_G1);
    const float* g2s = reinterpret_cast<const float*>(smem + OFF_G2);
    #pragma unroll
    for (int mm = 0; mm < 2; ++mm)
        #pragma unroll
        for (int hf = 0; hf < 2; ++hf) {
            int row = wm * 32 + mm * 16 + (lane >> 2) + hf * 8;
            float g1 = g1s[row], g2 = g2s[row];
            int grow = row0 + row;
            if (grow < N) {
                float* orow = out + (size_t)grow * 256;
                #pragma unroll
                for (int nn = 0; nn < 8; ++nn) {
                    float2 v;
                    v.x = g1 * acc[mm][nn][hf * 2 + 0] + g2 * bb[nn][0];
                    v.y = g1 * acc[mm][nn][hf * 2 + 1] + g2 * bb[nn][1];
                    *reinterpret_cast<float2*>(orow + wn * 64 + nn * 8 + (lane & 3) * 2) = v;
                }
            }
        }
}

extern "C" void kernel_launch(void* const* d_in, const int* in_sizes, int n_in,
                              void* d_out, int out_size) {
    const float* x = (const float*)d_in[0];
    const float* W = (const float*)d_in[1];
    const float* b = (const float*)d_in[2];
    float* out = (float*)d_out;
    int N = in_sizes[0] / 256;

    cudaFuncSetAttribute(hyp_mma_kernel, cudaFuncAttributeMaxDynamicSharedMemorySize, SMEM_TOTAL);

    dim3 wgrid(8, 8);
    wsplit_kernel<<<wgrid, 256>>>(W);
    int grid = (N + 63) / 64;
    hyp_mma_kernel<<<grid, 256, SMEM_TOTAL>>>(x, b, out, N);
}